// round 8
// baseline (speedup 1.0000x reference)
#include <cuda_runtime.h>
#include <math.h>

// Fixed problem shapes
#define BS     4
#define C_     64
#define H_     64
#define W_     64
#define HW     4096     // H*W
#define NPTS   4096
#define M_TOT  (BS*HW)  // 16384

#define CELL   4
#define GRIDC  16       // 64/CELL
#define NCELL  (GRIDC*GRIDC)
#define CAND_CAP 768    // smem candidate cap (expected ~144)

#define LRELU_SLOPE 0.1f

// ---------------- device scratch (no allocations allowed) ----------------
__device__ float  g_f3t[BS * NPTS * C_];       // feat_3d transposed [b][n][c] (4 MB)
__device__ float4 g_cpts[BS * NPTS];           // binned points (u,v,u2,idx)  (256 KB)
__device__ int    g_cstart[BS][NCELL + 1];     // cell start offsets
__device__ int    g_knn[M_TOT * 3];            // knn indices

// ---------------- K1: bin points into 16x16 cells (counting sort) ----------------
// one block of 512 threads per batch; 8 points per thread
__global__ void bin_points(const float* __restrict__ uv) {
    __shared__ int cnt[NCELL], off[NCELL];
    __shared__ int sA[NCELL], sB[NCELL];
    int b = blockIdx.x;
    int t = threadIdx.x;          // 512
    const float* uvb = uv + (size_t)b * 2 * NPTS;

    if (t < NCELL) cnt[t] = 0;
    __syncthreads();

    int mycell[8];
    #pragma unroll
    for (int i = 0; i < 8; i++) {
        int n = t + i * 512;
        float u = uvb[n], v = uvb[NPTS + n];
        int cx = (int)(u * 0.25f);            // exact power-of-2 scale
        int cy = (int)(v * 0.25f);
        int c = cy * GRIDC + cx;
        mycell[i] = c;
        atomicAdd(&cnt[c], 1);
    }
    __syncthreads();

    // inclusive scan over 256 cells (first 256 threads)
    if (t < NCELL) sA[t] = cnt[t];
    __syncthreads();
    int* srcp = sA; int* dstp = sB;
    #pragma unroll
    for (int ofs = 1; ofs < NCELL; ofs <<= 1) {
        if (t < NCELL) {
            int v = srcp[t];
            if (t >= ofs) v += srcp[t - ofs];
            dstp[t] = v;
        }
        __syncthreads();
        int* tmp = srcp; srcp = dstp; dstp = tmp;
    }
    if (t < NCELL) {
        int excl = srcp[t] - cnt[t];
        off[t] = excl;
        g_cstart[b][t] = excl;
        if (t == NCELL - 1) g_cstart[b][NCELL] = srcp[NCELL - 1];
    }
    __syncthreads();

    #pragma unroll
    for (int i = 0; i < 8; i++) {
        int n = t + i * 512;
        int c = mycell[i];
        int pos = atomicAdd(&off[c], 1);
        float u = uvb[n], v = uvb[NPTS + n];
        g_cpts[(size_t)b * NPTS + pos] =
            make_float4(u, v,
                        __fadd_rn(__fmul_rn(u, u), __fmul_rn(v, v)),
                        __int_as_float(n));
    }
}

// ---------------- K2: knn_search (blocks 0..1023) + transpose (1024..2047) ----------------
// knn: one block per (b, cell): 16 queries, 8 threads each.
// d rounding identical to validated version:
//   cross = fma(fy, v, rn(fx*u)); d = rn(rn(g2+u2) - rn(2*cross))
// Selection: (d, idx) lexicographic -> order-independent, matches top_k ties.
// transpose: 32x32 tiles of feat_3d (b,C,N)->(b,N,C), float4 both ways.
#define INS(dv, iv)                                                     \
    if ((dv) < d2 || ((dv) == d2 && (iv) < i2)) {                       \
        if ((dv) < d1 || ((dv) == d1 && (iv) < i1)) {                   \
            d2 = d1; i2 = i1;                                           \
            if ((dv) < d0 || ((dv) == d0 && (iv) < i0)) {               \
                d1 = d0; i1 = i0; d0 = (dv); i0 = (iv);                 \
            } else { d1 = (dv); i1 = (iv); }                            \
        } else { d2 = (dv); i2 = (iv); }                                \
    }

__global__ void knn_transpose(const float* __restrict__ f3) {
    __shared__ float4 cand[CAND_CAP];
    __shared__ int s_total;
    __shared__ float tile[32][33];

    int tid = threadIdx.x;          // 128

    if (blockIdx.x >= 1024) {
        // ---------------- transpose path ----------------
        int tix = blockIdx.x - 1024;          // 0..1023
        int b   = tix >> 8;
        int rem = tix & 255;
        int c0  = (rem >> 7) * 32;
        int n0  = (rem & 127) * 32;
        const float* src = f3 + ((size_t)(b * C_ + c0)) * NPTS + n0;
        #pragma unroll
        for (int k = 0; k < 2; k++) {
            int idx  = tid + k * 128;         // 0..255
            int row  = idx >> 3;              // c within tile
            int col4 = idx & 7;               // float4 slot along n
            float4 v = *(const float4*)(src + row * NPTS + col4 * 4);
            tile[row][col4 * 4 + 0] = v.x;
            tile[row][col4 * 4 + 1] = v.y;
            tile[row][col4 * 4 + 2] = v.z;
            tile[row][col4 * 4 + 3] = v.w;
        }
        __syncthreads();
        float* dst = g_f3t + ((size_t)(b * NPTS + n0)) * C_ + c0;
        #pragma unroll
        for (int k = 0; k < 2; k++) {
            int idx  = tid + k * 128;
            int n    = idx >> 3;              // n within tile
            int col4 = idx & 7;               // float4 slot along c
            float4 v = make_float4(tile[col4 * 4 + 0][n],
                                   tile[col4 * 4 + 1][n],
                                   tile[col4 * 4 + 2][n],
                                   tile[col4 * 4 + 3][n]);
            *(float4*)(dst + n * C_ + col4 * 4) = v;
        }
        return;
    }

    // ---------------- knn path ----------------
    int b    = blockIdx.x >> 8;
    int cell = blockIdx.x & 255;
    int cx = cell & (GRIDC - 1), cy = cell >> 4;

    const float4* pts = g_cpts + (size_t)b * NPTS;
    const int*    cs  = g_cstart[b];

    // ---- stage 3x3 neighborhood into smem ----
    int xlo = max(cx - 1, 0), xhi = min(cx + 1, GRIDC - 1);
    int ylo = max(cy - 1, 0), yhi = min(cy + 1, GRIDC - 1);
    int rs[3], rc_[3], rb[3], nrows = 0, total = 0;
    for (int y = ylo; y <= yhi; y++) {
        int s = cs[y * GRIDC + xlo];
        int e = cs[y * GRIDC + xhi + 1];
        rs[nrows] = s; rc_[nrows] = e - s; rb[nrows] = total;
        total += e - s; nrows++;
    }
    bool fits = (total <= CAND_CAP);
    if (fits) {
        for (int k = 0; k < nrows; k++)
            for (int i = tid; i < rc_[k]; i += 128)
                cand[rb[k] + i] = pts[rs[k] + i];
    }
    if (tid == 0) s_total = total;
    __syncthreads();

    // ---- per-query scan: group g = query, 8 threads/query ----
    int g   = tid >> 3;             // 0..15
    int sub = tid & 7;
    int px = cx * CELL + (g & 3);
    int py = cy * CELL + (g >> 2);
    float fx = (float)px, fy = (float)py;
    float g2 = fx * fx + fy * fy;   // exact (small ints)

    float d0 = 3.4e38f, d1 = 3.4e38f, d2 = 3.4e38f;
    int   i0 = 0x7fffffff, i1 = 0x7fffffff, i2 = 0x7fffffff;

    if (fits) {
        int T = s_total;
        for (int p = sub; p < T; p += 8) {
            float4 P = cand[p];
            float cross = __fmaf_rn(fy, P.y, __fmul_rn(fx, P.x));
            float d = __fsub_rn(__fadd_rn(g2, P.z), __fadd_rn(cross, cross));
            int idx = __float_as_int(P.w);
            INS(d, idx);
        }
    } else {
        // overflow slow path: scan gmem ranges directly (never hit in practice)
        for (int k = 0; k < nrows; k++)
            for (int p = sub; p < rc_[k]; p += 8) {
                float4 P = pts[rs[k] + p];
                float cross = __fmaf_rn(fy, P.y, __fmul_rn(fx, P.x));
                float d = __fsub_rn(__fadd_rn(g2, P.z), __fadd_rn(cross, cross));
                int idx = __float_as_int(P.w);
                INS(d, idx);
            }
    }

    // ---- merge 8 partial top-3 lists (shfl-down tree, width 8) ----
    #pragma unroll
    for (int off = 4; off > 0; off >>= 1) {
        float e0 = __shfl_down_sync(0xffffffffu, d0, off, 8);
        int   j0 = __shfl_down_sync(0xffffffffu, i0, off, 8);
        float e1 = __shfl_down_sync(0xffffffffu, d1, off, 8);
        int   j1 = __shfl_down_sync(0xffffffffu, i1, off, 8);
        float e2 = __shfl_down_sync(0xffffffffu, d2, off, 8);
        int   j2 = __shfl_down_sync(0xffffffffu, i2, off, 8);
        INS(e0, j0);
        INS(e1, j1);
        INS(e2, j2);
    }

    if (sub == 0) {
        // ---- rare fallback: rings >= 2, same bound as validated version ----
        for (int rc = 2; rc < GRIDC; rc++) {
            float lb = (float)(CELL * (rc - 1));
            if (lb * lb > d2 + 0.5f) break;   // false while d2 = INF
            int Xlo = max(cx - rc, 0), Xhi = min(cx + rc, GRIDC - 1);
            int Ylo = max(cy - rc, 0), Yhi = min(cy + rc, GRIDC - 1);
            for (int y = Ylo; y <= Yhi; y++) {
                if (y == cy - rc || y == cy + rc) {
                    int ps = cs[y * GRIDC + Xlo], pe = cs[y * GRIDC + Xhi + 1];
                    for (int p = ps; p < pe; p++) {
                        float4 P = pts[p];
                        float cross = __fmaf_rn(fy, P.y, __fmul_rn(fx, P.x));
                        float d = __fsub_rn(__fadd_rn(g2, P.z), __fadd_rn(cross, cross));
                        int idx = __float_as_int(P.w);
                        INS(d, idx);
                    }
                } else {
                    if (cx - rc >= 0) {
                        int c = y * GRIDC + (cx - rc);
                        for (int p = cs[c]; p < cs[c + 1]; p++) {
                            float4 P = pts[p];
                            float cross = __fmaf_rn(fy, P.y, __fmul_rn(fx, P.x));
                            float d = __fsub_rn(__fadd_rn(g2, P.z), __fadd_rn(cross, cross));
                            int idx = __float_as_int(P.w);
                            INS(d, idx);
                        }
                    }
                    if (cx + rc <= GRIDC - 1) {
                        int c = y * GRIDC + (cx + rc);
                        for (int p = cs[c]; p < cs[c + 1]; p++) {
                            float4 P = pts[p];
                            float cross = __fmaf_rn(fy, P.y, __fmul_rn(fx, P.x));
                            float d = __fsub_rn(__fadd_rn(g2, P.z), __fadd_rn(cross, cross));
                            int idx = __float_as_int(P.w);
                            INS(d, idx);
                        }
                    }
                }
            }
        }
        int m = b * HW + py * 64 + px;
        g_knn[m * 3] = i0; g_knn[m * 3 + 1] = i1; g_knn[m * 3 + 2] = i2;
    }
}
#undef INS

// ---------------- K3: fused score MLP + gather + out GEMM ----------------
// 256 blocks x 256 threads; each block owns 64 queries (m-tile).
// Phase 1 (per warp, 8 queries, shfl z-path): write flo/fhi into swizzled Fs.
// Phase 2: register-tiled GEMM out = lrelu(w_out @ F + b_out) from smem.
__global__ void fused_score_gemm(const float* __restrict__ uv,
                                 const float* __restrict__ w1, const float* __restrict__ b1,
                                 const float* __restrict__ w2, const float* __restrict__ b2,
                                 const float* __restrict__ w_out,
                                 const float* __restrict__ b_out,
                                 float* __restrict__ out) {
    __shared__ float Wt[64 * 64];     // [c][o] for LDS.128 reads
    __shared__ float Fs[64 * 64];     // swizzled: row r, col (c+r)&63

    int tid  = threadIdx.x;
    int lane = tid & 31;
    int wid  = tid >> 5;              // 8 warps
    int m0   = blockIdx.x * 64;

    // stage W transpose (independent of score phase)
    for (int idx = tid; idx < 4096; idx += 256) {
        int o = idx >> 6, c = idx & 63;
        Wt[c * 64 + o] = w_out[idx];
    }

    // ---- phase 1: score (shfl variant, QPW=8) ----
    int i_mine = lane & 15;
    int j_mine = lane >> 4;
    float w1a = w1[i_mine * 3 + 0];
    float w1b = w1[i_mine * 3 + 1];
    float w1c = w1[i_mine * 3 + 2];
    float b1r = b1[i_mine];
    float w2lo[16], w2hi[16];
    #pragma unroll
    for (int i = 0; i < 16; i++) {
        w2lo[i] = w2[lane * 16 + i];
        w2hi[i] = w2[(lane + 32) * 16 + i];
    }
    float b2lo = b2[lane], b2hi = b2[lane + 32];

    int base_m = m0 + wid * 8;
    #pragma unroll
    for (int t = 0; t < 8; t++) {
        int m = base_m + t;                // 0..16383
        int b = m >> 12;
        int q = m & 4095;
        float fx = (float)(q & 63);
        float fy = (float)(q >> 6);

        int n0 = __ldg(&g_knn[m * 3]);
        int n1 = __ldg(&g_knn[m * 3 + 1]);
        int n2 = __ldg(&g_knn[m * 3 + 2]);
        const float* uvb = uv + (size_t)b * 2 * NPTS;

        // feature gathers (coalesced per warp; independent of MLP chain)
        const float* f0 = g_f3t + ((size_t)(b * NPTS + n0)) * C_;
        const float* f1 = g_f3t + ((size_t)(b * NPTS + n1)) * C_;
        const float* f2 = g_f3t + ((size_t)(b * NPTS + n2)) * C_;
        float f0lo = f0[lane], f0hi = f0[lane + 32];
        float f1lo = f1[lane], f1hi = f1[lane + 32];
        float f2lo = f2[lane], f2hi = f2[lane + 32];

        // h for my (i_mine, j_mine) neighbor
        int   na = j_mine ? n1 : n0;
        float ua = uvb[na], va = uvb[NPTS + na];
        float oxa = ua - fx, oya = va - fy;
        float nrma = sqrtf(oxa * oxa + oya * oya);
        float ha = fmaf(w1c, nrma, fmaf(w1b, oya, w1a * oxa)) + b1r;
        ha = ha >= 0.f ? ha : LRELU_SLOPE * ha;
        // h for (i_mine, j=2)
        float ub = uvb[n2], vb = uvb[NPTS + n2];
        float oxb = ub - fx, oyb = vb - fy;
        float nrmb = sqrtf(oxb * oxb + oyb * oyb);
        float hb = fmaf(w1c, nrmb, fmaf(w1b, oyb, w1a * oxb)) + b1r;
        hb = hb >= 0.f ? hb : LRELU_SLOPE * hb;

        float zlo0 = b2lo, zlo1 = b2lo, zlo2 = b2lo;
        float zhi0 = b2hi, zhi1 = b2hi, zhi2 = b2hi;
        #pragma unroll
        for (int i = 0; i < 16; i++) {
            float h0 = __shfl_sync(0xffffffffu, ha, i);
            float h1 = __shfl_sync(0xffffffffu, ha, 16 + i);
            float h2 = __shfl_sync(0xffffffffu, hb, i);
            zlo0 = fmaf(w2lo[i], h0, zlo0);
            zlo1 = fmaf(w2lo[i], h1, zlo1);
            zlo2 = fmaf(w2lo[i], h2, zlo2);
            zhi0 = fmaf(w2hi[i], h0, zhi0);
            zhi1 = fmaf(w2hi[i], h1, zhi1);
            zhi2 = fmaf(w2hi[i], h2, zhi2);
        }
        float s0lo = 1.f / (1.f + __expf(-zlo0));
        float s1lo = 1.f / (1.f + __expf(-zlo1));
        float s2lo = 1.f / (1.f + __expf(-zlo2));
        float s0hi = 1.f / (1.f + __expf(-zhi0));
        float s1hi = 1.f / (1.f + __expf(-zhi1));
        float s2hi = 1.f / (1.f + __expf(-zhi2));

        float flo = fmaf(s2lo, f2lo, fmaf(s1lo, f1lo, s0lo * f0lo));
        float fhi = fmaf(s2hi, f2hi, fmaf(s1hi, f1hi, s0hi * f0hi));

        int r = wid * 8 + t;               // row within tile
        Fs[r * 64 + ((lane + r) & 63)]      = flo;
        Fs[r * 64 + ((lane + 32 + r) & 63)] = fhi;
    }
    __syncthreads();

    // ---- phase 2: GEMM (64 rows x 64 out-channels) ----
    int mi = lane;
    int og = wid;                     // uniform per warp -> broadcast LDS for W
    float acc[2][8];
    #pragma unroll
    for (int j = 0; j < 2; j++)
        #pragma unroll
        for (int oi = 0; oi < 8; oi++) acc[j][oi] = 0.f;

    #pragma unroll 8
    for (int c = 0; c < 64; c++) {
        float4 wv0 = *(const float4*)&Wt[c * 64 + og * 8];
        float4 wv1 = *(const float4*)&Wt[c * 64 + og * 8 + 4];
        #pragma unroll
        for (int j = 0; j < 2; j++) {
            int r = mi + 32 * j;
            float f = Fs[r * 64 + ((c + r) & 63)];
            acc[j][0] = fmaf(wv0.x, f, acc[j][0]);
            acc[j][1] = fmaf(wv0.y, f, acc[j][1]);
            acc[j][2] = fmaf(wv0.z, f, acc[j][2]);
            acc[j][3] = fmaf(wv0.w, f, acc[j][3]);
            acc[j][4] = fmaf(wv1.x, f, acc[j][4]);
            acc[j][5] = fmaf(wv1.y, f, acc[j][5]);
            acc[j][6] = fmaf(wv1.z, f, acc[j][6]);
            acc[j][7] = fmaf(wv1.w, f, acc[j][7]);
        }
    }
    #pragma unroll
    for (int oi = 0; oi < 8; oi++) {
        int o = og * 8 + oi;
        float bo = __ldg(&b_out[o]);
        #pragma unroll
        for (int j = 0; j < 2; j++) {
            int m = m0 + mi + 32 * j;
            int b = m >> 12;
            int q = m & 4095;
            float v = acc[j][oi] + bo;
            v = v >= 0.f ? v : LRELU_SLOPE * v;
            out[((size_t)(b * 64 + o) << 12) + q] = v;
        }
    }
}

// ---------------- launch ----------------
extern "C" void kernel_launch(void* const* d_in, const int* in_sizes, int n_in,
                              void* d_out, int out_size) {
    const float* uv      = (const float*)d_in[0];
    // d_in[1] = feat_2d: shape-only in reference, unused
    const float* feat_3d = (const float*)d_in[2];
    const float* w1      = (const float*)d_in[3];
    const float* b1      = (const float*)d_in[4];
    const float* w2      = (const float*)d_in[5];
    const float* b2      = (const float*)d_in[6];
    const float* w_out   = (const float*)d_in[7];
    const float* b_out   = (const float*)d_in[8];
    float* out = (float*)d_out;

    bin_points<<<BS, 512>>>(uv);
    knn_transpose<<<2048, 128>>>(feat_3d);
    fused_score_gemm<<<M_TOT / 64, 256>>>(uv, w1, b1, w2, b2, w_out, b_out, out);
}